// round 8
// baseline (speedup 1.0000x reference)
#include <cuda_runtime.h>

// Problem constants (from reference)
#define VOCAB   512
#define MAXLEN  512
#define BATCH   128
#define NFEAT   (VOCAB + VOCAB * VOCAB + 2)   // 262658

// One CTA per batch row, 512 threads, one position per thread (best measured
// shape). Neighbor action loaded directly as an independent 4B load with a
// clamped index (no divergent branch). Butterfly shuffle reductions; (sum,max)
// partials packed as float2 in smem so stage 2 does one LDS.64 per lane.
// Epilogue scalars are prefetched before the final butterfly stage so their
// latency overlaps the reduction instead of serializing after it.
__global__ __launch_bounds__(512, 2)
void lr_ngram_kernel(const float* __restrict__ x,
                     const int*   __restrict__ lengths,
                     const float* __restrict__ W,
                     const float* __restrict__ bias,
                     float*       __restrict__ out)
{
    __shared__ float2 s_part[16];          // (sum, max) per warp

    const int b    = blockIdx.x;
    const int j    = threadIdx.x;          // position, 0..511
    const int lane = j & 31;
    const int wid  = j >> 5;
    const int len  = lengths[b];

    const float* __restrict__ xr = x + (size_t)b * MAXLEN * 2;

    // Two independent loads, issued back-to-back (clamped neighbor index:
    // j=511 re-reads its own action; that bigram is masked out anyway).
    const int jn = (j + 1 < MAXLEN) ? j + 1 : j;
    float2 at  = reinterpret_cast<const float2*>(xr)[j];     // (a_j, t_j)
    float  anf = __ldg(&xr[jn * 2]);                         // a_{j+1}

    int a  = (int)at.x;
    int an = (int)anf;

    // Gathers: unigram + bigram, independent of each other.
    float sum = 0.0f;
    if (j < len)     sum += W[a];
    if (j + 1 < len) sum += W[VOCAB + (a << 9) + an];

    float tmax = (j < len) ? at.y : -3.402823466e38f;

    // Stage 1: butterfly warp reduction (sum + max interleaved).
    const unsigned m = 0xffffffffu;
    #pragma unroll
    for (int off = 16; off > 0; off >>= 1) {
        sum  += __shfl_xor_sync(m, sum, off);
        tmax  = fmaxf(tmax, __shfl_xor_sync(m, tmax, off));
    }
    if (lane == 0) s_part[wid] = make_float2(sum, tmax);
    __syncthreads();

    // Stage 2: 16 partials reduced by the first half-warp of warp 0.
    if (wid == 0 && lane < 16) {
        // Prefetch epilogue scalars early; independent of the reduction below.
        float w_time = __ldg(&W[NFEAT - 2]);
        float w_cnt  = __ldg(&W[NFEAT - 1]);
        float bs     = __ldg(&bias[0]);

        float2 p = s_part[lane];
        sum  = p.x;
        tmax = p.y;
        #pragma unroll
        for (int off = 8; off > 0; off >>= 1) {
            sum  += __shfl_xor_sync(0x0000ffffu, sum, off);
            tmax  = fmaxf(tmax, __shfl_xor_sync(0x0000ffffu, tmax, off));
        }
        if (lane == 0) {
            out[b] = sum + tmax * w_time + (float)len * w_cnt + bs;
        }
    }
}

extern "C" void kernel_launch(void* const* d_in, const int* in_sizes, int n_in,
                              void* d_out, int out_size)
{
    const float* x       = (const float*)d_in[0];   // [B, MAXLEN, 2] f32
    const int*   lengths = (const int*)  d_in[1];   // [B] i32
    const float* W       = (const float*)d_in[2];   // [1, F] f32
    const float* bias    = (const float*)d_in[3];   // [1] f32
    float*       out     = (float*)d_out;           // [B, 1] f32

    lr_ngram_kernel<<<BATCH, 512>>>(x, lengths, W, bias, out);
}

// round 9
// speedup vs baseline: 1.1192x; 1.1192x over previous
#include <cuda_runtime.h>

// Problem constants (from reference)
#define VOCAB   512
#define MAXLEN  512
#define BATCH   128
#define NFEAT   (VOCAB + VOCAB * VOCAB + 2)   // 262658

// FINAL (locked, best cold time of series: 5.504us, 284 GB/s).
// One CTA per batch row, 512 threads, one position per thread.
// The dot product feat@W collapses to a gather-reduce: never materialize
// the [B, 262658] feature tensor.
//  - two independent loads per thread (8B x, 4B neighbor action, clamped
//    index -> no divergent branch), issued back-to-back so the bigram
//    gather waits on max(load_lat), not load -> shfl -> gather;
//  - unigram + bigram gathers independent, predicated on length;
//  - combined (sum, max) shfl_down warp reduction, 16-partial smem tail.
__global__ __launch_bounds__(512, 2)
void lr_ngram_kernel(const float* __restrict__ x,
                     const int*   __restrict__ lengths,
                     const float* __restrict__ W,
                     const float* __restrict__ bias,
                     float*       __restrict__ out)
{
    __shared__ float s_sum[16];
    __shared__ float s_max[16];

    const int b    = blockIdx.x;
    const int j    = threadIdx.x;          // position, 0..511
    const int lane = j & 31;
    const int wid  = j >> 5;
    const int len  = lengths[b];

    const float* __restrict__ xr = x + (size_t)b * MAXLEN * 2;

    // Two independent loads, issued back-to-back (clamped neighbor index:
    // j=511 re-reads its own action; that bigram is masked out anyway).
    const int jn = (j + 1 < MAXLEN) ? j + 1 : j;
    float2 at  = reinterpret_cast<const float2*>(xr)[j];     // (a_j, t_j)
    float  anf = __ldg(&xr[jn * 2]);                         // a_{j+1}

    int a  = (int)at.x;
    int an = (int)anf;

    // Gathers: unigram + bigram, independent of each other.
    float sum = 0.0f;
    if (j < len)     sum += W[a];
    if (j + 1 < len) sum += W[VOCAB + (a << 9) + an];

    float tmax = (j < len) ? at.y : -3.402823466e38f;

    // Warp reduction (sum + max together).
    const unsigned m = 0xffffffffu;
    #pragma unroll
    for (int off = 16; off > 0; off >>= 1) {
        sum  += __shfl_down_sync(m, sum, off);
        tmax  = fmaxf(tmax, __shfl_down_sync(m, tmax, off));
    }
    if (lane == 0) { s_sum[wid] = sum; s_max[wid] = tmax; }
    __syncthreads();

    // Final reduction across 16 warps by warp 0.
    if (wid == 0) {
        sum  = (lane < 16) ? s_sum[lane] : 0.0f;
        tmax = (lane < 16) ? s_max[lane] : -3.402823466e38f;
        #pragma unroll
        for (int off = 8; off > 0; off >>= 1) {
            sum  += __shfl_down_sync(m, sum, off);
            tmax  = fmaxf(tmax, __shfl_down_sync(m, tmax, off));
        }
        if (lane == 0) {
            out[b] = sum
                   + tmax * W[NFEAT - 2]
                   + (float)len * W[NFEAT - 1]
                   + bias[0];
        }
    }
}

extern "C" void kernel_launch(void* const* d_in, const int* in_sizes, int n_in,
                              void* d_out, int out_size)
{
    const float* x       = (const float*)d_in[0];   // [B, MAXLEN, 2] f32
    const int*   lengths = (const int*)  d_in[1];   // [B] i32
    const float* W       = (const float*)d_in[2];   // [1, F] f32
    const float* bias    = (const float*)d_in[3];   // [1] f32
    float*       out     = (float*)d_out;           // [B, 1] f32

    lr_ngram_kernel<<<BATCH, 512>>>(x, lengths, W, bias, out);
}

// round 10
// speedup vs baseline: 1.1250x; 1.0052x over previous
#include <cuda_runtime.h>

// Problem constants (from reference)
#define VOCAB   512
#define MAXLEN  512
#define BATCH   128
#define NFEAT   (VOCAB + VOCAB * VOCAB + 2)   // 262658

// One CTA per batch row, 512 threads, one position per thread.
// Key change vs locked R9: the W gathers are issued UNCONDITIONALLY and the
// length mask is applied after the loads return. This removes the
// lengths-load -> predicate -> gather serialization (a full L2 round trip)
// from the warm critical path; lengths now loads in parallel with x.
// Index safety: actions are valid ids in [0,512) at every position, so the
// unigram index < 512 and the bigram index <= 262655 < NFEAT-2. Never OOB,
// never touches the tail scalars.
__global__ __launch_bounds__(512, 2)
void lr_ngram_kernel(const float* __restrict__ x,
                     const int*   __restrict__ lengths,
                     const float* __restrict__ W,
                     const float* __restrict__ bias,
                     float*       __restrict__ out)
{
    __shared__ float s_sum[16];
    __shared__ float s_max[16];

    const int b    = blockIdx.x;
    const int j    = threadIdx.x;          // position, 0..511
    const int lane = j & 31;
    const int wid  = j >> 5;

    const float* __restrict__ xr = x + (size_t)b * MAXLEN * 2;

    // Independent loads, all issued before anything depends on them:
    // x pair, neighbor action, and lengths (no longer gates the gathers).
    const int jn = (j + 1 < MAXLEN) ? j + 1 : j;
    float2 at  = reinterpret_cast<const float2*>(xr)[j];     // (a_j, t_j)
    float  anf = __ldg(&xr[jn * 2]);                         // a_{j+1}
    const int len = __ldg(&lengths[b]);

    int a  = (int)at.x;
    int an = (int)anf;

    // Unconditional gathers (indices always in-range); mask afterwards.
    float wu = W[a];                                // unigram weight
    float wb = W[VOCAB + (a << 9) + an];            // bigram weight

    float sum = ((j     < len) ? wu : 0.0f)
              + ((j + 1 < len) ? wb : 0.0f);
    float tmax = (j < len) ? at.y : -3.402823466e38f;

    // Warp reduction (sum + max together).
    const unsigned m = 0xffffffffu;
    #pragma unroll
    for (int off = 16; off > 0; off >>= 1) {
        sum  += __shfl_down_sync(m, sum, off);
        tmax  = fmaxf(tmax, __shfl_down_sync(m, tmax, off));
    }
    if (lane == 0) { s_sum[wid] = sum; s_max[wid] = tmax; }
    __syncthreads();

    // Final reduction across 16 warps by warp 0.
    if (wid == 0) {
        sum  = (lane < 16) ? s_sum[lane] : 0.0f;
        tmax = (lane < 16) ? s_max[lane] : -3.402823466e38f;
        #pragma unroll
        for (int off = 8; off > 0; off >>= 1) {
            sum  += __shfl_down_sync(m, sum, off);
            tmax  = fmaxf(tmax, __shfl_down_sync(m, tmax, off));
        }
        if (lane == 0) {
            out[b] = sum
                   + tmax * W[NFEAT - 2]
                   + (float)len * W[NFEAT - 1]
                   + bias[0];
        }
    }
}

extern "C" void kernel_launch(void* const* d_in, const int* in_sizes, int n_in,
                              void* d_out, int out_size)
{
    const float* x       = (const float*)d_in[0];   // [B, MAXLEN, 2] f32
    const int*   lengths = (const int*)  d_in[1];   // [B] i32
    const float* W       = (const float*)d_in[2];   // [1, F] f32
    const float* bias    = (const float*)d_in[3];   // [1] f32
    float*       out     = (float*)d_out;           // [B, 1] f32

    lr_ngram_kernel<<<BATCH, 512>>>(x, lengths, W, bias, out);
}